// round 3
// baseline (speedup 1.0000x reference)
#include <cuda_runtime.h>

// x[8,1,160,160,160] fp32, log_sigma[3] -> scalar RBF slice-smoothness loss.
#define BATCH 8
#define S 160
#define PLANE (S * S)            // 25600
#define NPAIR (S - 1)            // 159
#define NACC (BATCH * NPAIR)     // 1272
#define W4 40                    // float4 per row
#define ROWS 8                   // rows per strip
#define THREADS (W4 * ROWS)      // 320
#define STRIPS (S / ROWS)        // 20
#define NCHUNK 4
#define DCHUNK (S / NCHUNK)      // 40
#define NBLOCKS (STRIPS * NCHUNK * BATCH)  // 640

// Accumulators (device globals; zero-initialized; re-zeroed by last block each launch).
__device__ float g_sqD[NACC];
__device__ float g_sqH[NACC];
__device__ float g_sqW[NACC];
__device__ unsigned int g_count;

__device__ __forceinline__ float warp_sum(float v) {
    v += __shfl_xor_sync(0xffffffffu, v, 16);
    v += __shfl_xor_sync(0xffffffffu, v, 8);
    v += __shfl_xor_sync(0xffffffffu, v, 4);
    v += __shfl_xor_sync(0xffffffffu, v, 2);
    v += __shfl_xor_sync(0xffffffffu, v, 1);
    return v;
}

// Block: strip of 8 rows x 160 cols of one plane, marching through a 40-plane d-chunk.
// Thread = one float4 position (h, 4c..4c+3). Every x element loaded once from DRAM.
//   D: register-carried prev plane; per-plane warp butterfly + lane0 RED.
//   H: double-buffered smem exchange (tid+40); boundary row h0+8 re-loaded (L2 hit).
//   W: float4-internal + 1 shfl (lane31 scalar patch).
__global__ void __launch_bounds__(THREADS, 4)
fused_kernel(const float* __restrict__ x,
             const float* __restrict__ log_sigma,
             float* __restrict__ out) {
    const int strip = blockIdx.x;
    const int chunk = blockIdx.y;
    const int b     = blockIdx.z;
    const int tid   = threadIdx.x;
    const int lane  = tid & 31;
    const int r     = tid / W4;
    const int c     = tid - r * W4;
    const int h     = strip * ROWS + r;

    const int d0     = chunk * DCHUNK;
    const int dstart = (chunk == 0) ? 0 : (d0 - 1);   // overlap plane for D pairing
    const int dend   = d0 + DCHUNK;
    const int niter  = dend - dstart;                 // 40 or 41

    __shared__ float4 sbuf[2][THREADS];   // H exchange, double-buffered
    __shared__ float  sWp[ROWS][S];       // per-row W partials (flat [r][pair]; slot 159 unused)
    __shared__ float  sH[ROWS];
    __shared__ float  sRed[THREADS / 32];
    __shared__ unsigned int sLast;

    if (tid < ROWS) sH[tid] = 0.0f;

    // thread's base address in plane dstart
    const float* pcur = x + ((size_t)(b * S) + dstart) * PLANE + h * S + 4 * c;
    const bool topr = (r == ROWS - 1) && (h + 1 < S);   // owns boundary H pair (h, h+1)

    float aw0 = 0.f, aw1 = 0.f, aw2 = 0.f, aw3 = 0.f, aH = 0.f;

    // 2-deep software pipeline: keep 2 independent LDG.128 in flight per thread.
    float4 v  = *(const float4*)pcur;
    float4 vn = (niter > 1) ? *(const float4*)(pcur + PLANE) : v;
    const float* pf = pcur + 2 * (size_t)PLANE;
    float4 vprev = v;

    for (int i = 0; i < niter; ++i) {
        const int p = dstart + i;

        // prefetch plane p+2 BEFORE the barrier
        float4 vnn = make_float4(0.f, 0.f, 0.f, 0.f);
        if (i + 2 < niter) vnn = *(const float4*)pf;
        pf += PLANE;

        const int par = i & 1;
        sbuf[par][tid] = v;

        // D diff vs previous plane (registers only; pre-barrier)
        float dd = 0.f;
        if (i > 0) {
            float t;
            t = v.x - vprev.x; dd  = t * t;
            t = v.y - vprev.y; dd += t * t;
            t = v.z - vprev.z; dd += t * t;
            t = v.w - vprev.w; dd += t * t;
        }
        dd = warp_sum(dd);
        if (i > 0 && lane == 0) atomicAdd(&g_sqD[b * NPAIR + (p - 1)], dd);

        __syncthreads();

        if (p >= d0) {   // overlap plane contributes D only
            float t;
            // W: internal pairs + boundary via shfl (lane31 patched from L1)
            float nx = __shfl_down_sync(0xffffffffu, v.x, 1);
            if (lane == 31 && c < W4 - 1) nx = pcur[4];
            t = v.y - v.x; aw0 += t * t;
            t = v.z - v.y; aw1 += t * t;
            t = v.w - v.z; aw2 += t * t;
            if (c < W4 - 1) { t = nx - v.w; aw3 += t * t; }

            // H: row r+1 from smem; boundary row h0+8 reloaded (next strip's row -> L2 hit)
            if (r < ROWS - 1) {
                const float4 u = sbuf[par][tid + W4];
                t = u.x - v.x; aH += t * t;
                t = u.y - v.y; aH += t * t;
                t = u.z - v.z; aH += t * t;
                t = u.w - v.w; aH += t * t;
            } else if (topr) {
                const float4 u = *(const float4*)(pcur + S);
                t = u.x - v.x; aH += t * t;
                t = u.y - v.y; aH += t * t;
                t = u.z - v.z; aH += t * t;
                t = u.w - v.w; aH += t * t;
            }
        }

        vprev = v; v = vn; vn = vnn;
        pcur += PLANE;
    }

    // ---- flush W: per-row partials -> smem -> one atomic per pair ----
    ((float4*)sWp[r])[c] = make_float4(aw0, aw1, aw2, aw3);   // slot 4c..4c+3
    // ---- flush H: shared accumulate per row slot ----
    atomicAdd(&sH[r], aH);
    __syncthreads();

    if (tid < NPAIR) {
        float s = 0.f;
        #pragma unroll
        for (int rr = 0; rr < ROWS; ++rr) s += sWp[rr][tid];
        atomicAdd(&g_sqW[b * NPAIR + tid], s);
    }
    if (tid < ROWS) {
        const int hh = strip * ROWS + tid;
        if (hh < NPAIR) atomicAdd(&g_sqH[b * NPAIR + hh], sH[tid]);
    }

    // ---- completion counter: last block finalizes + resets state ----
    __threadfence();
    if (tid == 0) sLast = (atomicAdd(&g_count, 1u) == (unsigned)(NBLOCKS - 1));
    __syncthreads();
    if (sLast) {
        __threadfence();
        const float c0 = 0.5f * __expf(-2.f * log_sigma[0]);  // axis D
        const float c1 = 0.5f * __expf(-2.f * log_sigma[1]);  // axis H
        const float c2 = 0.5f * __expf(-2.f * log_sigma[2]);  // axis W
        float acc = 0.f;
        for (int i = tid; i < NACC; i += THREADS) {
            acc += expf(-g_sqD[i] * c0) + expf(-g_sqH[i] * c1) + expf(-g_sqW[i] * c2);
            g_sqD[i] = 0.f; g_sqH[i] = 0.f; g_sqW[i] = 0.f;   // reset for next replay
        }
        acc = warp_sum(acc);
        if (lane == 0) sRed[tid >> 5] = acc;
        __syncthreads();
        if (tid == 0) {
            float tot = 0.f;
            #pragma unroll
            for (int wgi = 0; wgi < THREADS / 32; ++wgi) tot += sRed[wgi];
            out[0] = -tot / (float)(NACC * 3);
            g_count = 0u;
        }
    }
}

extern "C" void kernel_launch(void* const* d_in, const int* in_sizes, int n_in,
                              void* d_out, int out_size) {
    const float* x         = (const float*)d_in[0];   // [8,1,160,160,160] fp32
    const float* log_sigma = (const float*)d_in[1];   // [3] fp32
    float* out             = (float*)d_out;           // scalar fp32

    dim3 grid(STRIPS, NCHUNK, BATCH);
    fused_kernel<<<grid, THREADS>>>(x, log_sigma, out);
}

// round 4
// speedup vs baseline: 1.8155x; 1.8155x over previous
#include <cuda_runtime.h>

// x[8,1,160,160,160] fp32, log_sigma[3] -> scalar RBF slice-smoothness loss.
#define BATCH 8
#define S 160
#define PLANE (S * S)              // 25600
#define NPAIR (S - 1)              // 159
#define NACC (BATCH * NPAIR)       // 1272
#define NCHUNK 18
#define CH 9                       // owned planes per chunk (last chunk: 7)
#define GROUPS 20                  // row groups per plane
#define RPT 8                      // rows per thread (contiguous)
#define W4 40                      // float4 columns per row
#define THREADS 800                // GROUPS * W4
#define NWARPS (THREADS / 32)      // 25
#define NBLOCKS (NCHUNK * BATCH)   // 144 (single wave on 148 SMs)

// Accumulators (device globals; zero-initialized; reset by last block each launch).
__device__ float g_sqD[NACC];
__device__ float g_sqH[NACC];
__device__ float g_sqW[NACC];
__device__ unsigned int g_count;

__device__ __forceinline__ float warp_sum(float v) {
    v += __shfl_xor_sync(0xffffffffu, v, 16);
    v += __shfl_xor_sync(0xffffffffu, v, 8);
    v += __shfl_xor_sync(0xffffffffu, v, 4);
    v += __shfl_xor_sync(0xffffffffu, v, 2);
    v += __shfl_xor_sync(0xffffffffu, v, 1);
    return v;
}

// Block = one full plane footprint, marching over a chunk of d.
// Thread (g, c): rows [8g, 8g+8), float4 column c. Each x element: ONE strided LDG.128.
//   D: register-carried across planes (cur[8]); per-plane warp butterfly + lane0 RED.
//   H: 7 internal pairs register-carried; boundary pair via 1 extra float4 (L1/L2 hit).
//   W: float4-internal + shfl_down (lane31 patched; c=39 has no boundary pair).
// No barriers, no smem in the main loop.
__global__ void __launch_bounds__(THREADS, 1)
fused_kernel(const float* __restrict__ x,
             const float* __restrict__ log_sigma,
             float* __restrict__ out) {
    const int chunk = blockIdx.x;
    const int b     = blockIdx.y;
    const int tid   = threadIdx.x;
    const int lane  = tid & 31;
    const int g     = tid / W4;
    const int c     = tid - g * W4;

    const int d0     = chunk * CH;
    const int n_own  = min(CH, S - d0);          // 9 (last chunk: 7)
    const int n_load = min(CH + 1, S - d0);      // 10 (last chunk: 7)

    __shared__ float sW[THREADS * 4];            // per-thread W partials (float4 layout)
    __shared__ float sH[THREADS * 9];            // per-thread H partials, pad 9 (conflict-free)
    __shared__ float sRed[NWARPS];
    __shared__ unsigned int sLast;

    const float* p0 = x + ((size_t)(b * S + d0)) * PLANE
                        + (size_t)(RPT * g) * S + 4 * c;
    const bool hasBrow = (g < GROUPS - 1);       // owns boundary H pair (8g+7, 8g+8)
    const bool hasWb   = (c < W4 - 1);           // owns boundary W pair (4c+3, 4c+4)
    const bool patch   = (lane == 31) && hasWb;  // shfl src crosses warp -> scalar load

    float4 cur[RPT];
    float aH[RPT];
    #pragma unroll
    for (int j = 0; j < RPT; ++j) aH[j] = 0.f;
    float aw0 = 0.f, aw1 = 0.f, aw2 = 0.f, aw3 = 0.f;

    for (int i = 0; i < n_load; ++i) {
        const float* pp = p0 + (size_t)i * PLANE;
        const bool own = (i < n_own);            // uniform across block
        float dAcc = 0.f;
        float4 prev;
        float t;
        #pragma unroll
        for (int j = 0; j < RPT; ++j) {
            const float4 v = *(const float4*)(pp + j * S);
            if (i > 0) {                          // D diff vs previous plane
                t = v.x - cur[j].x; dAcc += t * t;
                t = v.y - cur[j].y; dAcc += t * t;
                t = v.z - cur[j].z; dAcc += t * t;
                t = v.w - cur[j].w; dAcc += t * t;
            }
            if (own) {
                // W diffs
                float nx = __shfl_down_sync(0xffffffffu, v.x, 1);
                if (patch) nx = pp[j * S + 4];
                t = v.y - v.x; aw0 += t * t;
                t = v.z - v.y; aw1 += t * t;
                t = v.w - v.z; aw2 += t * t;
                if (hasWb) { t = nx - v.w; aw3 += t * t; }
                // H internal pairs (rows j-1, j)
                if (j > 0) {
                    t = v.x - prev.x; aH[j - 1] += t * t;
                    t = v.y - prev.y; aH[j - 1] += t * t;
                    t = v.z - prev.z; aH[j - 1] += t * t;
                    t = v.w - prev.w; aH[j - 1] += t * t;
                }
            }
            prev = v;
            cur[j] = v;
        }
        // H boundary pair (8g+7, 8g+8): neighbor group's first row (L1/L2 hit)
        if (own && hasBrow) {
            const float4 vb = *(const float4*)(pp + RPT * S);
            t = vb.x - prev.x; aH[RPT - 1] += t * t;
            t = vb.y - prev.y; aH[RPT - 1] += t * t;
            t = vb.z - prev.z; aH[RPT - 1] += t * t;
            t = vb.w - prev.w; aH[RPT - 1] += t * t;
        }
        // D: one butterfly + one RED per warp per plane (1024 elems amortized)
        if (i > 0) {
            dAcc = warp_sum(dAcc);
            if (lane == 0) atomicAdd(&g_sqD[b * NPAIR + d0 + i - 1], dAcc);
        }
    }

    // ---- one-time flush: smem transpose, then one global atomic per pair ----
    ((float4*)sW)[tid] = make_float4(aw0, aw1, aw2, aw3);   // conflict-free STS.128
    #pragma unroll
    for (int s = 0; s < RPT; ++s) sH[tid * 9 + s] = aH[s];  // stride 9: conflict-free
    __syncthreads();

    if (tid < NPAIR) {
        // W pair tid = 4*cc+q, owned by threads (g, cc) for all g
        float vw = 0.f;
        #pragma unroll
        for (int gg = 0; gg < GROUPS; ++gg) vw += sW[gg * (W4 * 4) + tid];
        atomicAdd(&g_sqW[b * NPAIR + tid], vw);
        // H pair tid = 8*g2+s, owned by threads (g2, c) for all c
        const int g2 = tid >> 3, s = tid & 7;
        float vh = 0.f;
        #pragma unroll
        for (int cc = 0; cc < W4; ++cc) vh += sH[(g2 * W4 + cc) * 9 + s];
        atomicAdd(&g_sqH[b * NPAIR + tid], vh);
    }

    // ---- completion counter: last block finalizes + resets state ----
    __threadfence();
    if (tid == 0) sLast = (atomicAdd(&g_count, 1u) == (unsigned)(NBLOCKS - 1));
    __syncthreads();
    if (sLast) {
        __threadfence();
        const float c0 = 0.5f * __expf(-2.f * log_sigma[0]);  // axis D
        const float c1 = 0.5f * __expf(-2.f * log_sigma[1]);  // axis H
        const float c2 = 0.5f * __expf(-2.f * log_sigma[2]);  // axis W
        float acc = 0.f;
        for (int i = tid; i < NACC; i += THREADS) {
            acc += expf(-g_sqD[i] * c0) + expf(-g_sqH[i] * c1) + expf(-g_sqW[i] * c2);
            g_sqD[i] = 0.f; g_sqH[i] = 0.f; g_sqW[i] = 0.f;   // reset for next replay
        }
        acc = warp_sum(acc);
        if (lane == 0) sRed[tid >> 5] = acc;
        __syncthreads();
        if (tid == 0) {
            float tot = 0.f;
            #pragma unroll
            for (int wgi = 0; wgi < NWARPS; ++wgi) tot += sRed[wgi];
            out[0] = -tot / (float)(NACC * 3);
            g_count = 0u;
        }
    }
}

extern "C" void kernel_launch(void* const* d_in, const int* in_sizes, int n_in,
                              void* d_out, int out_size) {
    const float* x         = (const float*)d_in[0];   // [8,1,160,160,160] fp32
    const float* log_sigma = (const float*)d_in[1];   // [3] fp32
    float* out             = (float*)d_out;           // scalar fp32

    dim3 grid(NCHUNK, BATCH);
    fused_kernel<<<grid, THREADS>>>(x, log_sigma, out);
}